// round 14
// baseline (speedup 1.0000x reference)
#include <cuda_runtime.h>
#include <cuda_fp16.h>

// PatternDetector: B=131072 rows x L=256 int32 in [0,40). Output Bx4 f32.
//
// Stable "nonzeros-first" argsort preserves order -> all features are
// functions of consecutive-nonzero pairs -> forward scan per row.
// dec = (n-1) - rep - inc.
//
// R14 = R10 (TPB=64, 16-row tiles, persistent, 2-stage cp.async double
// buffer, 64 elem/thread) WITHOUT the repack phase: the scan reads raw
// int32 directly from slotted smem.
// Slot = 64 elems * 4B = 256B data padded to 272B (68 words): LDS.128
// phase groups hit bank-group (17*l mod 8) = l mod 8 -> conflict-free.
// Scan: chains A (elems 0-31) and B (32-63) SIMD'd in one half2
// recurrence (value = 1024+v exact = 0x6400|v; masks via set.*.u32.f16x2;
// prev blend = 1 LOP3; counters packed u16x2 via vsub2).

constexpr int TPB        = 64;     // threads = chunks per tile
constexpr int ROWS_TILE  = 16;
constexpr int L_LEN      = 256;
constexpr int TILE_INT4  = ROWS_TILE * L_LEN / 4;   // 1024
constexpr int SLOT_B     = 272;    // 64-elem chunk slot (256 data + 16 pad)
constexpr int BUF_B      = TPB * SLOT_B;            // 17408
constexpr int GRID       = 912;    // 152 SM x 6 blocks

__device__ __forceinline__ unsigned heq2_mask(unsigned a, unsigned b) {
    unsigned d; asm("set.eq.u32.f16x2 %0, %1, %2;" : "=r"(d) : "r"(a), "r"(b)); return d;
}
__device__ __forceinline__ unsigned hgt2_mask(unsigned a, unsigned b) {
    unsigned d; asm("set.gt.u32.f16x2 %0, %1, %2;" : "=r"(d) : "r"(a), "r"(b)); return d;
}
__device__ __forceinline__ unsigned hne2_mask(unsigned a, unsigned b) {
    unsigned d; asm("set.ne.u32.f16x2 %0, %1, %2;" : "=r"(d) : "r"(a), "r"(b)); return d;
}

// last two nonzeros among 4 ints (ascending position), count
__device__ __forceinline__ void last2nz_int4(int4 q, int& p1, int& p2, int& cnt)
{
    int vv[4] = {q.x, q.y, q.z, q.w};
    p1 = 0; p2 = 0; cnt = 0;
    #pragma unroll
    for (int k = 0; k < 4; ++k) {
        int v = vv[k];
        bool nz = (v != 0);
        p2 = nz ? p1 : p2;
        p1 = nz ? v  : p1;
        cnt += nz;
    }
}

// rare fallback: walk this row's ints (slotted smem) backward from elem j0
__device__ __noinline__ void walk_back(const unsigned char* rowbase, int j0,
                                       int& o1, int& o2)
{
    o1 = 127; o2 = 127;
    int f = 0;
    for (int j = j0; j >= 0 && f < 2; --j) {
        int v = *(const int*)(rowbase + (j >> 6) * SLOT_B + (j & 63) * 4);
        if (v) { if (!f) o1 = v; else o2 = v; ++f; }
    }
}

// issue one tile (16 cp.async.cg of 16B per thread) + commit
__device__ __forceinline__ void issue_tile(const char* gsrc, unsigned smem_dst)
{
    #pragma unroll
    for (int i = 0; i < TILE_INT4 / TPB; ++i) {       // 16 per thread
        int idx = i * TPB + (int)threadIdx.x;         // int4 index in tile
        unsigned dst = smem_dst + (unsigned)(idx >> 4) * SLOT_B
                                + (unsigned)(idx & 15) * 16;
        asm volatile("cp.async.cg.shared.global [%0], [%1], 16;"
                     :: "r"(dst), "l"(gsrc + (size_t)idx * 16));
    }
    asm volatile("cp.async.commit_group;" ::: "memory");
}

__global__ void __launch_bounds__(TPB, 6) pattern_kernel(
    const int4* __restrict__ x4, float4* __restrict__ out, int total_tiles)
{
    __shared__ unsigned char smem[2 * BUF_B];         // 34816 B
    const unsigned smem_u = (unsigned)__cvta_generic_to_shared(smem);

    const int tid = threadIdx.x;
    const int cr  = tid & 3;                          // chunk within row

    int t = blockIdx.x;
    if (t < total_tiles)
        issue_tile((const char*)(x4 + (long long)t * TILE_INT4), smem_u);

    int buf = 0;
    for (; t < total_tiles; t += GRID, buf ^= 1) {
        // wait for current buffer's copy; the barrier also proves every
        // thread finished scanning buf^1 last iteration (safe to refill).
        asm volatile("cp.async.wait_group 0;" ::: "memory");
        __syncthreads();

        int tn = t + GRID;
        if (tn < total_tiles)
            issue_tile((const char*)(x4 + (long long)tn * TILE_INT4),
                       smem_u + (buf ^ 1) * BUF_B);

        const unsigned char* bufp    = smem + buf * BUF_B;
        const unsigned char* slot    = bufp + tid * SLOT_B;
        const unsigned char* rowbase = bufp + (tid & ~3) * SLOT_B;

        // ---- chain inits ----
        int a1 = 127, a2 = 127;                       // before chunk elem 0
        if (cr) {
            int4 q = *(const int4*)(slot - SLOT_B + 240);  // prev chunk 60..63
            int p1, p2, cnt;
            last2nz_int4(q, p1, p2, cnt);
            if (cnt >= 2) { a1 = p1; a2 = p2; }
            else walk_back(rowbase, cr * 64 - 1, a1, a2);
        }
        int b1, b2;                                   // before chunk elem 32
        {
            int4 q = *(const int4*)(slot + 112);           // own elems 28..31
            int p1, p2, cnt;
            last2nz_int4(q, p1, p2, cnt);
            if (cnt >= 2) { b1 = p1; b2 = p2; }
            else walk_back(rowbase, cr * 64 + 31, b1, b2);
        }

        // ---- SWAR scan: low half = chain A (0-31), high = B (32-63) ----
        const unsigned BIAS1 = 0x6400u;               // half 1024
        unsigned p1h = (unsigned)(BIAS1 | a1) | ((unsigned)(BIAS1 | b1) << 16);
        unsigned p2h = (unsigned)(BIAS1 | a2) | ((unsigned)(BIAS1 | b2) << 16);
        unsigned accR = 0, accI = 0, accP = 0, accN = 0;

        #pragma unroll
        for (int h = 0; h < 8; ++h) {
            int4 qa = *(const int4*)(slot + h * 16);         // elems 4h..4h+3
            int4 qb = *(const int4*)(slot + 128 + h * 16);   // elems 32+4h..
            int va[4] = {qa.x, qa.y, qa.z, qa.w};
            int vb[4] = {qb.x, qb.y, qb.z, qb.w};
            #pragma unroll
            for (int k = 0; k < 4; ++k) {
                unsigned vaa = (unsigned)va[k] | BIAS1;
                unsigned vbb = (unsigned)vb[k] | BIAS1;
                unsigned v   = vaa + (vbb << 16);     // {1024+va, 1024+vb}
                unsigned mR = heq2_mask(v, p1h);
                unsigned mI = hgt2_mask(v, p1h);
                unsigned mP = heq2_mask(v, p2h);
                unsigned mN = hne2_mask(v, 0x64006400u);
                accR = __vsub2(accR, mR);             // mask == -1 per u16
                accI = __vsub2(accI, mI);
                accP = __vsub2(accP, mP);
                accN = __vsub2(accN, mN);
                p2h = (p1h & mN) | (p2h & ~mN);       // single LOP3 each
                p1h = (v   & mN) | (p1h & ~mN);
            }
        }

        // ---- reduce the 4 chunk lanes of this row (u16 sums <= 256) ----
        #pragma unroll
        for (int m = 1; m <= 2; m <<= 1) {
            accR = __vadd2(accR, __shfl_xor_sync(0xffffffffu, accR, m));
            accI = __vadd2(accI, __shfl_xor_sync(0xffffffffu, accI, m));
            accP = __vadd2(accP, __shfl_xor_sync(0xffffffffu, accP, m));
            accN = __vadd2(accN, __shfl_xor_sync(0xffffffffu, accN, m));
        }

        if (cr == 0) {
            int REP = (int)(accR & 0xffffu) + (int)(accR >> 16);
            int INC = (int)(accI & 0xffffu) + (int)(accI >> 16);
            int PER = (int)(accP & 0xffffu) + (int)(accP >> 16);
            int N   = (int)(accN & 0xffffu) + (int)(accN >> 16);
            float o0 = 0.f, o1 = 0.f, o2 = 0.f, o3 = 0.f;
            if (N > 1) {
                int DEC  = (N - 1) - REP - INC;
                float d1 = 1.0f / (float)(N - 1);
                o0 = (float)REP * d1;
                o1 = (float)INC * d1;
                o2 = (float)DEC * d1;
                if (N >= 4) o3 = (float)PER / (float)(N - 2);
            }
            out[(long long)t * ROWS_TILE + (tid >> 2)] =
                make_float4(o0, o1, o2, o3);
        }
    }
}

extern "C" void kernel_launch(void* const* d_in, const int* in_sizes, int n_in,
                              void* d_out, int out_size)
{
    const int4* x = (const int4*)d_in[0];
    float4* out   = (float4*)d_out;
    const int total_elems = in_sizes[0];              // B * L
    const int nrows       = total_elems / L_LEN;      // 131072
    const int total_tiles = nrows / ROWS_TILE;        // 8192
    const int grid = (total_tiles < GRID) ? total_tiles : GRID;
    pattern_kernel<<<grid, TPB>>>(x, out, total_tiles);
}

// round 15
// speedup vs baseline: 1.0077x; 1.0077x over previous
#include <cuda_runtime.h>
#include <cuda_fp16.h>

// PatternDetector: B=131072 rows x L=256 int32 in [0,40). Output Bx4 f32.
//
// Stable "nonzeros-first" argsort preserves order -> all features are
// functions of consecutive-nonzero pairs -> single forward scan per row.
// dec = (n-1) - rep - inc.
//
// R15 = R5 (champion: 256 threads / 64 rows per block, byte-packed smem
// staging, two 32-elem chains per thread SIMD'd into one half2 recurrence;
// values as half 1024+v = bits 0x6400|v; exact __hfma2 blends) with
// __launch_bounds__(256,6): regs capped at 42 -> 6 blocks/SM = 48 warps
// (vs 40), attacking the warp-starvation that bounds issue at ~50%.

constexpr int TPB     = 256;
constexpr int RPB     = 64;
constexpr int L_LEN   = 256;
constexpr int CSTRIDE = 80;    // 64B chunk in 20-word slot: LDS.128 conflict-free

__device__ __forceinline__ __half2 h2bits(unsigned u) {
    return *reinterpret_cast<__half2*>(&u);
}
__device__ __forceinline__ unsigned bitsh2(__half2 h) {
    return *reinterpret_cast<unsigned*>(&h);
}

// branchless "last two nonzeros" of a 4-byte word (ascending position order)
__device__ __forceinline__ void last2nz_word(unsigned w, int& p1, int& p2, int& cnt)
{
    p1 = 0; p2 = 0; cnt = 0;
    #pragma unroll
    for (int k = 0; k < 4; ++k) {
        int v = (w >> (8 * k)) & 0xff;
        bool nz = (v != 0);
        p2 = nz ? p1 : p2;
        p1 = nz ? v  : p1;
        cnt += nz;
    }
}

__global__ void __launch_bounds__(TPB, 6) pattern_kernel(
    const int4* __restrict__ x4, float4* __restrict__ out)
{
    __shared__ unsigned char s[TPB * CSTRIDE];   // 20480 B
    const int tid = threadIdx.x;

    // ---- Stage: coalesced gmem -> byte-packed smem ----
    const int4* src = x4 + (long long)blockIdx.x * (RPB * L_LEN / 4);
    #pragma unroll
    for (int it = 0; it < 16; ++it) {
        int idx = it * TPB + tid;
        int4 v  = src[idx];
        unsigned lo = __byte_perm((unsigned)v.x, (unsigned)v.y, 0x0040);
        unsigned hi = __byte_perm((unsigned)v.z, (unsigned)v.w, 0x0040);
        unsigned packed = __byte_perm(lo, hi, 0x5410);
        *(unsigned*)&s[(idx >> 4) * CSTRIDE + (idx & 15) * 4] = packed;
    }
    __syncthreads();

    const int c         = tid & 3;      // chunk within row
    const int row_chunk = tid & ~3;

    // ---- Preload phase 1 ----
    const uint4* chunk = (const uint4*)&s[tid * CSTRIDE];
    uint4 q0 = chunk[0];
    uint4 q2 = chunk[2];

    // ---- Chain A init: last 2 nonzeros before element c*64 ----
    int a1 = 127, a2 = 127;
    if (c) {
        unsigned w = *(const unsigned*)&s[(tid - 1) * CSTRIDE + 60];
        int p1, p2, cnt;
        last2nz_word(w, p1, p2, cnt);
        if (cnt >= 2) { a1 = p1; a2 = p2; }
        else {
            int j = c * 64 - 1, found = 0;
            while (j >= 0 && found < 2) {
                int v = s[(row_chunk + (j >> 6)) * CSTRIDE + (j & 63)];
                if (v) { if (!found) a1 = v; else a2 = v; ++found; }
                --j;
            }
        }
    }

    // ---- Preload phase 2 ----
    uint4 q1 = chunk[1];
    uint4 q3 = chunk[3];

    // ---- Chain B init: last 2 nonzeros before element c*64+32 ----
    int b1 = 127, b2 = 127;
    {
        int p1, p2, cnt;
        last2nz_word(q1.w, p1, p2, cnt);   // elements 28..31 of this chunk
        if (cnt >= 2) { b1 = p1; b2 = p2; }
        else {
            int j = c * 64 + 31, found = 0;
            while (j >= 0 && found < 2) {
                int v = s[(row_chunk + (j >> 6)) * CSTRIDE + (j & 63)];
                if (v) { if (!found) b1 = v; else b2 = v; ++found; }
                --j;
            }
        }
    }

    // ---- Half2 chain state: low half = chain A, high half = chain B ----
    const unsigned BIAS = 0x64006400u;    // half2 {1024, 1024}
    const unsigned BMSK = 0x00FF00FFu;
    __half2 p1h = h2bits(((unsigned)(0x6400 | a1)) | ((unsigned)(0x6400 | b1) << 16));
    __half2 p2h = h2bits(((unsigned)(0x6400 | a2)) | ((unsigned)(0x6400 | b2) << 16));
    __half2 zero1024 = h2bits(BIAS);
    __half2 accR = h2bits(0u), accI = h2bits(0u);
    __half2 accP = h2bits(0u), accN = h2bits(0u);

    unsigned WA[8] = {q0.x, q0.y, q0.z, q0.w, q1.x, q1.y, q1.z, q1.w};
    unsigned WB[8] = {q2.x, q2.y, q2.z, q2.w, q3.x, q3.y, q3.z, q3.w};

    #pragma unroll
    for (int w = 0; w < 8; ++w) {
        unsigned wa = WA[w], wb = WB[w];
        #pragma unroll
        for (int k = 0; k < 4; ++k) {
            // interleave byte k of wa (chain A) and wb (chain B): PRMT
            unsigned pr = __byte_perm(wa, wb, 0x0400 + k * 0x0101);
            __half2 v  = h2bits((pr & BMSK) | BIAS);     // {1024+va, 1024+vb}
            accR = __hadd2(accR, __heq2(v, p1h));
            accI = __hadd2(accI, __hgt2(v, p1h));
            accP = __hadd2(accP, __heq2(v, p2h));
            __half2 nz = __hne2(v, zero1024);            // 1.0 if nonzero
            accN = __hadd2(accN, nz);
            p2h = __hfma2(nz, __hsub2(p1h, p2h), p2h);   // exact blends
            p1h = __hfma2(nz, __hsub2(v,   p1h), p1h);
        }
    }

    // ---- Reduce across the 4 chunk lanes (half2 adds stay exact, <=256) ----
    #pragma unroll
    for (int m = 1; m <= 2; m <<= 1) {
        accR = __hadd2(accR, h2bits(__shfl_xor_sync(0xffffffffu, bitsh2(accR), m)));
        accI = __hadd2(accI, h2bits(__shfl_xor_sync(0xffffffffu, bitsh2(accI), m)));
        accP = __hadd2(accP, h2bits(__shfl_xor_sync(0xffffffffu, bitsh2(accP), m)));
        accN = __hadd2(accN, h2bits(__shfl_xor_sync(0xffffffffu, bitsh2(accN), m)));
    }

    if (c == 0) {
        float REP = __half2float(__low2half(accR)) + __half2float(__high2half(accR));
        float INC = __half2float(__low2half(accI)) + __half2float(__high2half(accI));
        float PER = __half2float(__low2half(accP)) + __half2float(__high2half(accP));
        float NF  = __half2float(__low2half(accN)) + __half2float(__high2half(accN));
        int   N   = (int)NF;
        float o0 = 0.f, o1 = 0.f, o2 = 0.f, o3 = 0.f;
        if (N > 1) {
            float DEC = (NF - 1.0f) - REP - INC;
            float d1  = 1.0f / (NF - 1.0f);
            o0 = REP * d1;
            o1 = INC * d1;
            o2 = DEC * d1;
            if (N >= 4) o3 = PER / (NF - 2.0f);
        }
        out[(long long)blockIdx.x * RPB + (tid >> 2)] =
            make_float4(o0, o1, o2, o3);
    }
}

extern "C" void kernel_launch(void* const* d_in, const int* in_sizes, int n_in,
                              void* d_out, int out_size)
{
    const int4* x = (const int4*)d_in[0];
    float4* out   = (float4*)d_out;
    const int total_elems = in_sizes[0];      // B * L
    const int nrows  = total_elems / L_LEN;   // 131072
    const int blocks = nrows / RPB;           // 2048
    pattern_kernel<<<blocks, TPB>>>(x, out);
}

// round 16
// speedup vs baseline: 1.0749x; 1.0667x over previous
#include <cuda_runtime.h>
#include <cuda_fp16.h>

// PatternDetector: B=131072 rows x L=256 int32 in [0,40). Output Bx4 f32.
//
// Stable "nonzeros-first" argsort preserves order -> all features are
// functions of consecutive-nonzero pairs -> single forward scan per row.
// dec = (n-1) - rep - inc.
//
// R16 = R5 champion (256 threads / 64 rows per block, byte-packed smem
// staging, two 32-elem chains per thread SIMD'd into one half2 recurrence;
// values as half 1024+v = bits 0x6400|v, exact; __hfma2 blends; exact
// half2 counters) + __ldcs evict-first hint on the single-use input
// stream. Structure proven across 15 rounds to sit at the ~5.3 TB/s
// streaming ceiling for this access pattern.

constexpr int TPB     = 256;
constexpr int RPB     = 64;
constexpr int L_LEN   = 256;
constexpr int CSTRIDE = 80;    // 64B chunk in 20-word slot: LDS.128 conflict-free

__device__ __forceinline__ __half2 h2bits(unsigned u) {
    return *reinterpret_cast<__half2*>(&u);
}
__device__ __forceinline__ unsigned bitsh2(__half2 h) {
    return *reinterpret_cast<unsigned*>(&h);
}

// branchless "last two nonzeros" of a 4-byte word (ascending position order)
__device__ __forceinline__ void last2nz_word(unsigned w, int& p1, int& p2, int& cnt)
{
    p1 = 0; p2 = 0; cnt = 0;
    #pragma unroll
    for (int k = 0; k < 4; ++k) {
        int v = (w >> (8 * k)) & 0xff;
        bool nz = (v != 0);
        p2 = nz ? p1 : p2;
        p1 = nz ? v  : p1;
        cnt += nz;
    }
}

__global__ void __launch_bounds__(TPB, 5) pattern_kernel(
    const int4* __restrict__ x4, float4* __restrict__ out)
{
    __shared__ unsigned char s[TPB * CSTRIDE];   // 20480 B
    const int tid = threadIdx.x;

    // ---- Stage: coalesced gmem -> byte-packed smem (evict-first loads) ----
    const int4* src = x4 + (long long)blockIdx.x * (RPB * L_LEN / 4);
    #pragma unroll
    for (int it = 0; it < 16; ++it) {
        int idx = it * TPB + tid;
        int4 v  = __ldcs(&src[idx]);           // single-use stream: .cs
        unsigned packed = (unsigned)v.x | ((unsigned)v.y << 8)
                        | ((unsigned)v.z << 16) | ((unsigned)v.w << 24);
        *(unsigned*)&s[(idx >> 4) * CSTRIDE + (idx & 15) * 4] = packed;
    }
    __syncthreads();

    const int c         = tid & 3;      // chunk within row
    const int row_chunk = tid & ~3;

    // ---- Preload phase 1 ----
    const uint4* chunk = (const uint4*)&s[tid * CSTRIDE];
    uint4 q0 = chunk[0];
    uint4 q2 = chunk[2];

    // ---- Chain A init: last 2 nonzeros before element c*64 ----
    int a1 = 127, a2 = 127;
    if (c) {
        unsigned w = *(const unsigned*)&s[(tid - 1) * CSTRIDE + 60];
        int p1, p2, cnt;
        last2nz_word(w, p1, p2, cnt);
        if (cnt >= 2) { a1 = p1; a2 = p2; }
        else {
            int j = c * 64 - 1, found = 0;
            while (j >= 0 && found < 2) {
                int v = s[(row_chunk + (j >> 6)) * CSTRIDE + (j & 63)];
                if (v) { if (!found) a1 = v; else a2 = v; ++found; }
                --j;
            }
        }
    }

    // ---- Preload phase 2 ----
    uint4 q1 = chunk[1];
    uint4 q3 = chunk[3];

    // ---- Chain B init: last 2 nonzeros before element c*64+32 ----
    int b1 = 127, b2 = 127;
    {
        int p1, p2, cnt;
        last2nz_word(q1.w, p1, p2, cnt);   // elements 28..31 of this chunk
        if (cnt >= 2) { b1 = p1; b2 = p2; }
        else {
            int j = c * 64 + 31, found = 0;
            while (j >= 0 && found < 2) {
                int v = s[(row_chunk + (j >> 6)) * CSTRIDE + (j & 63)];
                if (v) { if (!found) b1 = v; else b2 = v; ++found; }
                --j;
            }
        }
    }

    // ---- Half2 chain state: low half = chain A, high half = chain B ----
    const unsigned BIAS = 0x64006400u;    // half2 {1024, 1024}
    const unsigned BMSK = 0x00FF00FFu;
    __half2 p1h = h2bits(((unsigned)(0x6400 | a1)) | ((unsigned)(0x6400 | b1) << 16));
    __half2 p2h = h2bits(((unsigned)(0x6400 | a2)) | ((unsigned)(0x6400 | b2) << 16));
    __half2 zero1024 = h2bits(BIAS);
    __half2 accR = h2bits(0u), accI = h2bits(0u);
    __half2 accP = h2bits(0u), accN = h2bits(0u);

    unsigned WA[8] = {q0.x, q0.y, q0.z, q0.w, q1.x, q1.y, q1.z, q1.w};
    unsigned WB[8] = {q2.x, q2.y, q2.z, q2.w, q3.x, q3.y, q3.z, q3.w};

    #pragma unroll
    for (int w = 0; w < 8; ++w) {
        unsigned wa = WA[w], wb = WB[w];
        #pragma unroll
        for (int k = 0; k < 4; ++k) {
            // interleave byte k of wa (chain A) and wb (chain B): PRMT
            unsigned pr = __byte_perm(wa, wb, 0x0400 + k * 0x0101);
            __half2 v  = h2bits((pr & BMSK) | BIAS);     // {1024+va, 1024+vb}
            accR = __hadd2(accR, __heq2(v, p1h));
            accI = __hadd2(accI, __hgt2(v, p1h));
            accP = __hadd2(accP, __heq2(v, p2h));
            __half2 nz = __hne2(v, zero1024);            // 1.0 if nonzero
            accN = __hadd2(accN, nz);
            p2h = __hfma2(nz, __hsub2(p1h, p2h), p2h);   // exact blends
            p1h = __hfma2(nz, __hsub2(v,   p1h), p1h);
        }
    }

    // ---- Reduce across the 4 chunk lanes (half2 adds stay exact, <=256) ----
    #pragma unroll
    for (int m = 1; m <= 2; m <<= 1) {
        accR = __hadd2(accR, h2bits(__shfl_xor_sync(0xffffffffu, bitsh2(accR), m)));
        accI = __hadd2(accI, h2bits(__shfl_xor_sync(0xffffffffu, bitsh2(accI), m)));
        accP = __hadd2(accP, h2bits(__shfl_xor_sync(0xffffffffu, bitsh2(accP), m)));
        accN = __hadd2(accN, h2bits(__shfl_xor_sync(0xffffffffu, bitsh2(accN), m)));
    }

    if (c == 0) {
        float REP = __half2float(__low2half(accR)) + __half2float(__high2half(accR));
        float INC = __half2float(__low2half(accI)) + __half2float(__high2half(accI));
        float PER = __half2float(__low2half(accP)) + __half2float(__high2half(accP));
        float NF  = __half2float(__low2half(accN)) + __half2float(__high2half(accN));
        int   N   = (int)NF;
        float o0 = 0.f, o1 = 0.f, o2 = 0.f, o3 = 0.f;
        if (N > 1) {
            float DEC = (NF - 1.0f) - REP - INC;
            float d1  = 1.0f / (NF - 1.0f);
            o0 = REP * d1;
            o1 = INC * d1;
            o2 = DEC * d1;
            if (N >= 4) o3 = PER / (NF - 2.0f);
        }
        out[(long long)blockIdx.x * RPB + (tid >> 2)] =
            make_float4(o0, o1, o2, o3);
    }
}

extern "C" void kernel_launch(void* const* d_in, const int* in_sizes, int n_in,
                              void* d_out, int out_size)
{
    const int4* x = (const int4*)d_in[0];
    float4* out   = (float4*)d_out;
    const int total_elems = in_sizes[0];      // B * L
    const int nrows  = total_elems / L_LEN;   // 131072
    const int blocks = nrows / RPB;           // 2048
    pattern_kernel<<<blocks, TPB>>>(x, out);
}